// round 5
// baseline (speedup 1.0000x reference)
#include <cuda_runtime.h>
#include <cuda_fp16.h>
#include <cstdint>

// ============================================================================
// GptOssMoEExperts: router collapses to identity (softmax over top-k sums to 1
// and the expert MLP is shared), so
//   out = ((x@Wg^T+bg) * silu(x@Wu^T+bu)) @ W2^T + b2
// GEMM1: CTA 128x128 (B tile = 64 gate rows + 64 up rows of same out cols),
//        warp tile 64x64, fused SiLU epilogue via smem exchange -> h fp16.
// GEMM2: CTA 128x96, warp tile 64x48 -> out fp32.
// mma.sync m16n8k16 fp16->fp32, cp.async 3-stage, 2 CTA/SM.
// ============================================================================

#define SEQ   4096
#define HID   2880
#define INTER 2880
#define NGU   (2 * INTER)   // 5760

static constexpr int BK     = 64;            // fp16 elems -> 128B rows
static constexpr int KIT    = HID / BK;      // 45
static constexpr int STAGES = 3;

// GEMM1 tile config
static constexpr int BM1     = 128;
static constexpr int BT1     = 128;                    // B tile rows (64 gate + 64 up)
static constexpr int OFF_B1  = BM1 * 128;              // 16384
static constexpr int STAGE1  = OFF_B1 + BT1 * 128;     // 32768
static constexpr int SMEM1   = STAGES * STAGE1;        // 98304

// GEMM2 tile config
static constexpr int BM2     = 128;
static constexpr int BN2     = 96;
static constexpr int OFF_B2  = BM2 * 128;              // 16384
static constexpr int STAGE2  = OFF_B2 + BN2 * 128;     // 28672
static constexpr int SMEM2   = STAGES * STAGE2;        // 86016

// ---------------------------------------------------------------------------
// Scratch (__device__ globals = sanctioned allocation-free scratch)
// ---------------------------------------------------------------------------
__device__ __align__(128) __half g_xh [(size_t)SEQ * HID];
__device__ __align__(128) __half g_w1h[(size_t)NGU * HID];
__device__ __align__(128) __half g_w2h[(size_t)HID * INTER];
__device__ __align__(128) __half g_hh [(size_t)SEQ * INTER];

// ---------------------------------------------------------------------------
// PTX helpers
// ---------------------------------------------------------------------------
__device__ __forceinline__ uint32_t smem_u32(const void* p) {
    uint32_t a;
    asm("{ .reg .u64 t; cvta.to.shared.u64 t, %1; cvt.u32.u64 %0, t; }" : "=r"(a) : "l"(p));
    return a;
}
__device__ __forceinline__ void ldsm4(uint32_t* r, uint32_t a) {
    asm volatile("ldmatrix.sync.aligned.m8n8.x4.shared.b16 {%0,%1,%2,%3}, [%4];"
                 : "=r"(r[0]), "=r"(r[1]), "=r"(r[2]), "=r"(r[3]) : "r"(a));
}
__device__ __forceinline__ void mma16816(float* d, const uint32_t* a, const uint32_t* b) {
    asm volatile(
        "mma.sync.aligned.m16n8k16.row.col.f32.f16.f16.f32 "
        "{%0,%1,%2,%3}, {%4,%5,%6,%7}, {%8,%9}, {%0,%1,%2,%3};"
        : "+f"(d[0]), "+f"(d[1]), "+f"(d[2]), "+f"(d[3])
        : "r"(a[0]), "r"(a[1]), "r"(a[2]), "r"(a[3]), "r"(b[0]), "r"(b[1]));
}
__device__ __forceinline__ void cp16(uint32_t s, const void* g) {
    asm volatile("cp.async.cg.shared.global [%0], [%1], 16;" :: "r"(s), "l"(g) : "memory");
}
#define CP_COMMIT()  asm volatile("cp.async.commit_group;" ::: "memory")
#define CP_WAIT_1()  asm volatile("cp.async.wait_group 1;"  ::: "memory")

// ---------------------------------------------------------------------------
// fp32 -> fp16 conversion (vectorized)
// ---------------------------------------------------------------------------
__global__ void cvt_kernel(const float4* __restrict__ src, uint2* __restrict__ dst, int n4) {
    int i = blockIdx.x * blockDim.x + threadIdx.x;
    if (i >= n4) return;
    float4 v = src[i];
    __half2 a = __floats2half2_rn(v.x, v.y);
    __half2 b = __floats2half2_rn(v.z, v.w);
    uint2 o;
    o.x = *reinterpret_cast<uint32_t*>(&a);
    o.y = *reinterpret_cast<uint32_t*>(&b);
    dst[i] = o;
}

// ---------------------------------------------------------------------------
// GEMM1 (fused): h[:, n:n+64] = (x@Wg^T+bg) * silu(x@Wu^T+bu) for 64 out cols.
// B tile rows 0-63 = W1 gate rows, 64-127 = W1 up rows (same global cols).
// 4 warps (2M x 2N), warp tile 64x64; wn=0 warps own gate cols, wn=1 up cols.
// Epilogue: up warps stage u+bias in smem, gate warps combine & store fp16.
// ---------------------------------------------------------------------------
__global__ void __launch_bounds__(128, 2)
gemm1_fused(const __half* __restrict__ A, const __half* __restrict__ W1,
            const float* __restrict__ b1, __half* __restrict__ h) {
    extern __shared__ __align__(128) char smem[];
    const uint32_t sb0 = smem_u32(smem);
    const int tid = threadIdx.x;
    const int l   = tid & 31;
    const int wid = tid >> 5;          // 0..3
    const int wm  = wid >> 1;          // 0..1
    const int wn  = wid & 1;           // 0..1
    const int mBase = blockIdx.x * BM1;
    const int nBase = blockIdx.y * 64;  // 64 output cols per CTA

    auto load_stage = [&](int kt, int slot) {
        const uint32_t sb = sb0 + slot * STAGE1;
        const int kc = kt * BK;
        #pragma unroll
        for (int k = 0; k < 8; k++) {                     // A: 1024 chunks
            int idx = tid + k * 128;
            int row = idx >> 3, u = idx & 7;
            cp16(sb + row * 128 + ((u ^ (row & 7)) << 4),
                 A + (size_t)(mBase + row) * HID + kc + u * 8);
        }
        #pragma unroll
        for (int k = 0; k < 8; k++) {                     // B: 1024 chunks
            int idx = tid + k * 128;
            int row = idx >> 3, u = idx & 7;
            int grow = (row < 64) ? (nBase + row) : (INTER + nBase + row - 64);
            cp16(sb + OFF_B1 + row * 128 + ((u ^ (row & 7)) << 4),
                 W1 + (size_t)grow * HID + kc + u * 8);
        }
    };

    const int l7  = l & 7;
    const int lhi = l >> 4;
    const int le  = l & 15;
    const int q   = l >> 3;
    const int aRow0 = wm * 64 + le;
    const int bRowO = wn * 64 + ((q >> 1) << 3) + l7;
    const int bUnit = q & 1;

    auto loadA = [&](uint32_t af[4][4], uint32_t sA, int ks) {
        #pragma unroll
        for (int i = 0; i < 4; i++)
            ldsm4(af[i], sA + (uint32_t)(aRow0 + i * 16) * 128 +
                           (uint32_t)(((ks * 2 + lhi) ^ l7) << 4));
    };
    auto loadB = [&](uint32_t bf[4][4], uint32_t sB, int ks) {
        #pragma unroll
        for (int p = 0; p < 4; p++)
            ldsm4(bf[p], sB + (uint32_t)(bRowO + p * 16) * 128 +
                           (uint32_t)(((ks * 2 + bUnit) ^ l7) << 4));
    };

    float acc[4][8][4] = {};
    uint32_t af[2][4][4], bf[2][4][4];

    #pragma unroll
    for (int s = 0; s < STAGES - 1; s++) {                // prologue
        load_stage(s, s);
        CP_COMMIT();
    }

    for (int kt = 0; kt < KIT; kt++) {
        CP_WAIT_1();
        __syncthreads();

        const int nk = kt + STAGES - 1;
        if (nk < KIT) load_stage(nk, nk % STAGES);
        CP_COMMIT();

        const uint32_t sA = sb0 + (kt % STAGES) * STAGE1;
        const uint32_t sB = sA + OFF_B1;

        loadA(af[0], sA, 0);
        loadB(bf[0], sB, 0);
        #pragma unroll
        for (int ks = 0; ks < 4; ks++) {
            const int cur = ks & 1, nxt = cur ^ 1;
            if (ks < 3) {
                loadA(af[nxt], sA, ks + 1);
                loadB(bf[nxt], sB, ks + 1);
            }
            #pragma unroll
            for (int i = 0; i < 4; i++)
                #pragma unroll
                for (int p = 0; p < 4; p++) {
                    mma16816(acc[i][2 * p],     af[cur][i], &bf[cur][p][0]);
                    mma16816(acc[i][2 * p + 1], af[cur][i], &bf[cur][p][2]);
                }
        }
    }

    // -------- epilogue: exchange up-half through smem, fused SiLU ----------
    __syncthreads();                       // all ldsm reads of stages done
    float* us = reinterpret_cast<float*>(smem);   // [128][66] padded fp32

    const int rL = wm * 64 + (l >> 2);
    const int cL = 2 * (l & 3);

    if (wn == 1) {                         // up warps: u + bias -> smem
        #pragma unroll
        for (int i = 0; i < 4; i++)
            #pragma unroll
            for (int j = 0; j < 8; j++) {
                const int c = cL + j * 8;
                const float bu0 = __ldg(b1 + INTER + nBase + c);
                const float bu1 = __ldg(b1 + INTER + nBase + c + 1);
                #pragma unroll
                for (int hh = 0; hh < 2; hh++) {
                    const int r = rL + i * 16 + hh * 8;
                    *reinterpret_cast<float2*>(&us[r * 66 + c]) =
                        make_float2(acc[i][j][2 * hh] + bu0,
                                    acc[i][j][2 * hh + 1] + bu1);
                }
            }
    }
    __syncthreads();
    if (wn == 0) {                         // gate warps: h = g*u*sigmoid(u)
        #pragma unroll
        for (int i = 0; i < 4; i++)
            #pragma unroll
            for (int j = 0; j < 8; j++) {
                const int c = cL + j * 8;
                const float bg0 = __ldg(b1 + nBase + c);
                const float bg1 = __ldg(b1 + nBase + c + 1);
                #pragma unroll
                for (int hh = 0; hh < 2; hh++) {
                    const int r = rL + i * 16 + hh * 8;
                    const float2 u = *reinterpret_cast<const float2*>(&us[r * 66 + c]);
                    const float g0 = acc[i][j][2 * hh]     + bg0;
                    const float g1 = acc[i][j][2 * hh + 1] + bg1;
                    const float h0 = g0 * u.x * (1.0f / (1.0f + __expf(-u.x)));
                    const float h1 = g1 * u.y * (1.0f / (1.0f + __expf(-u.y)));
                    *reinterpret_cast<__half2*>(
                        h + (size_t)(mBase + r) * INTER + nBase + c) =
                        __floats2half2_rn(h0, h1);
                }
            }
    }
}

// ---------------------------------------------------------------------------
// GEMM2: out = h @ W2^T + b2 (fp32). CTA 128x96, 4 warps (2x2), warp 64x48.
// ---------------------------------------------------------------------------
__global__ void __launch_bounds__(128, 2)
gemm2(const __half* __restrict__ A, const __half* __restrict__ B,
      const float* __restrict__ bias, float* __restrict__ oF) {
    extern __shared__ __align__(128) char smem[];
    const uint32_t sb0 = smem_u32(smem);
    const int tid = threadIdx.x;
    const int l   = tid & 31;
    const int wid = tid >> 5;
    const int wm  = wid >> 1;
    const int wn  = wid & 1;
    const int mBase = blockIdx.x * BM2;
    const int nBase = blockIdx.y * BN2;

    auto load_stage = [&](int kt, int slot) {
        const uint32_t sb = sb0 + slot * STAGE2;
        const int kc = kt * BK;
        #pragma unroll
        for (int k = 0; k < 8; k++) {                     // A: 1024 chunks
            int idx = tid + k * 128;
            int row = idx >> 3, u = idx & 7;
            cp16(sb + row * 128 + ((u ^ (row & 7)) << 4),
                 A + (size_t)(mBase + row) * HID + kc + u * 8);
        }
        #pragma unroll
        for (int k = 0; k < 6; k++) {                     // B: 768 chunks
            int idx = tid + k * 128;
            int row = idx >> 3, u = idx & 7;
            cp16(sb + OFF_B2 + row * 128 + ((u ^ (row & 7)) << 4),
                 B + (size_t)(nBase + row) * HID + kc + u * 8);
        }
    };

    const int l7  = l & 7;
    const int lhi = l >> 4;
    const int le  = l & 15;
    const int q   = l >> 3;
    const int aRow0 = wm * 64 + le;
    const int bRowO = wn * 48 + ((q >> 1) << 3) + l7;
    const int bUnit = q & 1;

    auto loadA = [&](uint32_t af[4][4], uint32_t sA, int ks) {
        #pragma unroll
        for (int i = 0; i < 4; i++)
            ldsm4(af[i], sA + (uint32_t)(aRow0 + i * 16) * 128 +
                           (uint32_t)(((ks * 2 + lhi) ^ l7) << 4));
    };
    auto loadB = [&](uint32_t bf[3][4], uint32_t sB, int ks) {
        #pragma unroll
        for (int p = 0; p < 3; p++)
            ldsm4(bf[p], sB + (uint32_t)(bRowO + p * 16) * 128 +
                           (uint32_t)(((ks * 2 + bUnit) ^ l7) << 4));
    };

    float acc[4][6][4] = {};
    uint32_t af[2][4][4], bf[2][3][4];

    #pragma unroll
    for (int s = 0; s < STAGES - 1; s++) {
        load_stage(s, s);
        CP_COMMIT();
    }

    for (int kt = 0; kt < KIT; kt++) {
        CP_WAIT_1();
        __syncthreads();

        const int nk = kt + STAGES - 1;
        if (nk < KIT) load_stage(nk, nk % STAGES);
        CP_COMMIT();

        const uint32_t sA = sb0 + (kt % STAGES) * STAGE2;
        const uint32_t sB = sA + OFF_B2;

        loadA(af[0], sA, 0);
        loadB(bf[0], sB, 0);
        #pragma unroll
        for (int ks = 0; ks < 4; ks++) {
            const int cur = ks & 1, nxt = cur ^ 1;
            if (ks < 3) {
                loadA(af[nxt], sA, ks + 1);
                loadB(bf[nxt], sB, ks + 1);
            }
            #pragma unroll
            for (int i = 0; i < 4; i++)
                #pragma unroll
                for (int p = 0; p < 3; p++) {
                    mma16816(acc[i][2 * p],     af[cur][i], &bf[cur][p][0]);
                    mma16816(acc[i][2 * p + 1], af[cur][i], &bf[cur][p][2]);
                }
        }
    }

    const int r00 = mBase + wm * 64 + (l >> 2);
    const int cB  = nBase + wn * 48 + 2 * (l & 3);

    #pragma unroll
    for (int i = 0; i < 4; i++)
        #pragma unroll
        for (int j = 0; j < 6; j++) {
            const int c = cB + j * 8;
            const float b0 = __ldg(bias + c), b1v = __ldg(bias + c + 1);
            #pragma unroll
            for (int hh = 0; hh < 2; hh++) {
                const int r = r00 + i * 16 + hh * 8;
                *reinterpret_cast<float2*>(oF + (size_t)r * HID + c) =
                    make_float2(acc[i][j][2 * hh] + b0,
                                acc[i][j][2 * hh + 1] + b1v);
            }
        }
}

// ---------------------------------------------------------------------------
// Host
// ---------------------------------------------------------------------------
extern "C" void kernel_launch(void* const* d_in, const int* in_sizes, int n_in,
                              void* d_out, int out_size) {
    const float* x  = (const float*)d_in[0];   // hidden_states (4096, 2880)
    const float* w1 = (const float*)d_in[3];   // gate_up_w (5760, 2880)
    const float* b1 = (const float*)d_in[4];   // gate_up_b (5760,)
    const float* w2 = (const float*)d_in[5];   // down_w (2880, 2880)
    const float* b2 = (const float*)d_in[6];   // down_b (2880,)
    float* out = (float*)d_out;                // (4096, 2880) fp32

    void *px, *pw1, *pw2, *ph;
    cudaGetSymbolAddress(&px,  g_xh);
    cudaGetSymbolAddress(&pw1, g_w1h);
    cudaGetSymbolAddress(&pw2, g_w2h);
    cudaGetSymbolAddress(&ph,  g_hh);

    // fp32 -> fp16
    {
        int n4 = (SEQ * HID) / 4;
        cvt_kernel<<<(n4 + 255) / 256, 256>>>((const float4*)x,  (uint2*)px,  n4);
        n4 = (NGU * HID) / 4;
        cvt_kernel<<<(n4 + 255) / 256, 256>>>((const float4*)w1, (uint2*)pw1, n4);
        n4 = (HID * INTER) / 4;
        cvt_kernel<<<(n4 + 255) / 256, 256>>>((const float4*)w2, (uint2*)pw2, n4);
    }

    cudaFuncSetAttribute(gemm1_fused,
                         cudaFuncAttributeMaxDynamicSharedMemorySize, SMEM1);
    cudaFuncSetAttribute(gemm2,
                         cudaFuncAttributeMaxDynamicSharedMemorySize, SMEM2);

    // GEMM1 fused: h = (x@Wg^T+bg) * silu(x@Wu^T+bu)   (fp16, 4096 x 2880)
    gemm1_fused<<<dim3(SEQ / BM1, INTER / 64), 128, SMEM1>>>(
        (const __half*)px, (const __half*)pw1, b1, (__half*)ph);

    // GEMM2: out = h @ W2^T + b2   (fp32, 4096 x 2880)
    gemm2<<<dim3(SEQ / BM2, HID / BN2), 128, SMEM2>>>(
        (const __half*)ph, (const __half*)pw2, b2, out);
}

// round 7
// speedup vs baseline: 1.0267x; 1.0267x over previous
#include <cuda_runtime.h>
#include <cuda_fp16.h>
#include <cstdint>

// ============================================================================
// GptOssMoEExperts: router collapses to identity (softmax over top-k sums to 1
// and the expert MLP is shared), so
//   out = ((x@Wg^T+bg) * silu(x@Wu^T+bu)) @ W2^T + b2
// GEMM1: R4 mainloop (CTA 128x96, warp 64x48, 2 CTA/SM) where the 96 B-rows =
//        48 gate rows + 48 up rows of the SAME 48 output columns; SiLU fused
//        in the epilogue via a smem exchange -> h fp16 directly.
// GEMM2: R4 config unchanged (CTA 128x96, warp 64x48) -> out fp32.
// mma.sync m16n8k16 fp16->fp32, cp.async 3-stage, 2 CTA/SM.
// R7 fix: R6 launched gemm1 with 25.6KB smem (bad constant) while the mainloop
// addresses 86KB -> illegal access. SMEM1 must be STAGES*STAGE; the 25.6KB
// epilogue exchange buffer lives inside that region.
// ============================================================================

#define SEQ   4096
#define HID   2880
#define INTER 2880
#define NGU   (2 * INTER)   // 5760

static constexpr int BM     = 128;
static constexpr int BN     = 96;            // B-tile rows
static constexpr int BK     = 64;            // fp16 elems -> 128B rows
static constexpr int KIT    = HID / BK;      // 45
static constexpr int STAGES = 3;
static constexpr int OFF_B  = BM * 128;               // 16384
static constexpr int STAGE  = OFF_B + BN * 128;       // 28672
static constexpr int SMEM_MAIN = STAGES * STAGE;      // 86016
static constexpr int SMEM1  = SMEM_MAIN;              // mainloop needs all 86016;
                                                      // epilogue buf (25.6KB) fits inside
static constexpr int SMEM2  = SMEM_MAIN;              // 86016

static_assert(128 * 50 * 4 <= SMEM1, "epilogue exchange buffer must fit");

// ---------------------------------------------------------------------------
// Scratch (__device__ globals = sanctioned allocation-free scratch)
// ---------------------------------------------------------------------------
__device__ __align__(128) __half g_xh [(size_t)SEQ * HID];
__device__ __align__(128) __half g_w1h[(size_t)NGU * HID];
__device__ __align__(128) __half g_w2h[(size_t)HID * INTER];
__device__ __align__(128) __half g_hh [(size_t)SEQ * INTER];

// ---------------------------------------------------------------------------
// PTX helpers
// ---------------------------------------------------------------------------
__device__ __forceinline__ uint32_t smem_u32(const void* p) {
    uint32_t a;
    asm("{ .reg .u64 t; cvta.to.shared.u64 t, %1; cvt.u32.u64 %0, t; }" : "=r"(a) : "l"(p));
    return a;
}
__device__ __forceinline__ void ldsm4(uint32_t* r, uint32_t a) {
    asm volatile("ldmatrix.sync.aligned.m8n8.x4.shared.b16 {%0,%1,%2,%3}, [%4];"
                 : "=r"(r[0]), "=r"(r[1]), "=r"(r[2]), "=r"(r[3]) : "r"(a));
}
__device__ __forceinline__ void mma16816(float* d, const uint32_t* a, const uint32_t* b) {
    asm volatile(
        "mma.sync.aligned.m16n8k16.row.col.f32.f16.f16.f32 "
        "{%0,%1,%2,%3}, {%4,%5,%6,%7}, {%8,%9}, {%0,%1,%2,%3};"
        : "+f"(d[0]), "+f"(d[1]), "+f"(d[2]), "+f"(d[3])
        : "r"(a[0]), "r"(a[1]), "r"(a[2]), "r"(a[3]), "r"(b[0]), "r"(b[1]));
}
__device__ __forceinline__ void cp16(uint32_t s, const void* g) {
    asm volatile("cp.async.cg.shared.global [%0], [%1], 16;" :: "r"(s), "l"(g) : "memory");
}
#define CP_COMMIT()  asm volatile("cp.async.commit_group;" ::: "memory")
#define CP_WAIT_1()  asm volatile("cp.async.wait_group 1;"  ::: "memory")

// ---------------------------------------------------------------------------
// fp32 -> fp16 conversion (vectorized)
// ---------------------------------------------------------------------------
__global__ void cvt_kernel(const float4* __restrict__ src, uint2* __restrict__ dst, int n4) {
    int i = blockIdx.x * blockDim.x + threadIdx.x;
    if (i >= n4) return;
    float4 v = src[i];
    __half2 a = __floats2half2_rn(v.x, v.y);
    __half2 b = __floats2half2_rn(v.z, v.w);
    uint2 o;
    o.x = *reinterpret_cast<uint32_t*>(&a);
    o.y = *reinterpret_cast<uint32_t*>(&b);
    dst[i] = o;
}

// ---------------------------------------------------------------------------
// GEMM1 (fused SiLU): CTA computes 48 output cols. B tile rows 0-47 = W1 gate
// rows (cols nBase..nBase+47), rows 48-95 = W1 up rows (same cols).
// 4 warps (2M x 2N), warp tile 64x48: wn=0 warps hold gate accs, wn=1 up accs.
// Mainloop identical to the proven R4 kernel. Epilogue: up warps stage u+bias
// in smem (stride 50 fp32), gate warps combine g*u*sigmoid(u) -> fp16 h.
// ---------------------------------------------------------------------------
__global__ void __launch_bounds__(128, 2)
gemm1_fused(const __half* __restrict__ A, const __half* __restrict__ W1,
            const float* __restrict__ b1, __half* __restrict__ h) {
    extern __shared__ __align__(128) char smem[];
    const uint32_t sb0 = smem_u32(smem);
    const int tid = threadIdx.x;
    const int l   = tid & 31;
    const int wid = tid >> 5;          // 0..3
    const int wm  = wid >> 1;          // 0..1
    const int wn  = wid & 1;           // 0..1
    const int mBase = blockIdx.x * BM;
    const int nBase = blockIdx.y * 48;  // 48 output cols per CTA

    auto load_stage = [&](int kt, int slot) {
        const uint32_t sb = sb0 + slot * STAGE;
        const int kc = kt * BK;
        #pragma unroll
        for (int k = 0; k < 8; k++) {                     // A: 1024 chunks
            int idx = tid + k * 128;
            int row = idx >> 3, u = idx & 7;
            cp16(sb + row * 128 + ((u ^ (row & 7)) << 4),
                 A + (size_t)(mBase + row) * HID + kc + u * 8);
        }
        #pragma unroll
        for (int k = 0; k < 6; k++) {                     // B: 768 chunks
            int idx = tid + k * 128;
            int row = idx >> 3, u = idx & 7;
            int grow = (row < 48) ? (nBase + row) : (INTER + nBase + row - 48);
            cp16(sb + OFF_B + row * 128 + ((u ^ (row & 7)) << 4),
                 W1 + (size_t)grow * HID + kc + u * 8);
        }
    };

    const int l7  = l & 7;
    const int lhi = l >> 4;
    const int le  = l & 15;
    const int q   = l >> 3;
    const int aRow0 = wm * 64 + le;
    const int bRowO = wn * 48 + ((q >> 1) << 3) + l7;
    const int bUnit = q & 1;

    auto loadA = [&](uint32_t af[4][4], uint32_t sA, int ks) {
        #pragma unroll
        for (int i = 0; i < 4; i++)
            ldsm4(af[i], sA + (uint32_t)(aRow0 + i * 16) * 128 +
                           (uint32_t)(((ks * 2 + lhi) ^ l7) << 4));
    };
    auto loadB = [&](uint32_t bf[3][4], uint32_t sB, int ks) {
        #pragma unroll
        for (int p = 0; p < 3; p++)
            ldsm4(bf[p], sB + (uint32_t)(bRowO + p * 16) * 128 +
                           (uint32_t)(((ks * 2 + bUnit) ^ l7) << 4));
    };

    float acc[4][6][4] = {};
    uint32_t af[2][4][4], bf[2][3][4];

    #pragma unroll
    for (int s = 0; s < STAGES - 1; s++) {                // prologue
        load_stage(s, s);
        CP_COMMIT();
    }

    for (int kt = 0; kt < KIT; kt++) {
        CP_WAIT_1();
        __syncthreads();

        const int nk = kt + STAGES - 1;
        if (nk < KIT) load_stage(nk, nk % STAGES);
        CP_COMMIT();

        const uint32_t sA = sb0 + (kt % STAGES) * STAGE;
        const uint32_t sB = sA + OFF_B;

        loadA(af[0], sA, 0);
        loadB(bf[0], sB, 0);
        #pragma unroll
        for (int ks = 0; ks < 4; ks++) {
            const int cur = ks & 1, nxt = cur ^ 1;
            if (ks < 3) {
                loadA(af[nxt], sA, ks + 1);
                loadB(bf[nxt], sB, ks + 1);
            }
            #pragma unroll
            for (int i = 0; i < 4; i++)
                #pragma unroll
                for (int p = 0; p < 3; p++) {
                    mma16816(acc[i][2 * p],     af[cur][i], &bf[cur][p][0]);
                    mma16816(acc[i][2 * p + 1], af[cur][i], &bf[cur][p][2]);
                }
        }
    }

    // -------- epilogue: exchange up-half through smem, fused SiLU ----------
    __syncthreads();                       // all ldsm reads of stages done
    float* us = reinterpret_cast<float*>(smem);   // [128][50] padded fp32

    const int rL = wm * 64 + (l >> 2);     // local row base (0..127)
    const int cL = 2 * (l & 3);            // local col base within 48

    if (wn == 1) {                         // up warps: u + bias -> smem
        #pragma unroll
        for (int j = 0; j < 6; j++) {
            const int c = cL + j * 8;
            const float bu0 = __ldg(b1 + INTER + nBase + c);
            const float bu1 = __ldg(b1 + INTER + nBase + c + 1);
            #pragma unroll
            for (int i = 0; i < 4; i++)
                #pragma unroll
                for (int hh = 0; hh < 2; hh++) {
                    const int r = rL + i * 16 + hh * 8;
                    us[r * 50 + c]     = acc[i][j][2 * hh]     + bu0;
                    us[r * 50 + c + 1] = acc[i][j][2 * hh + 1] + bu1;
                }
        }
    }
    __syncthreads();
    if (wn == 0) {                         // gate warps: h = g*u*sigmoid(u)
        #pragma unroll
        for (int j = 0; j < 6; j++) {
            const int c = cL + j * 8;
            const float bg0 = __ldg(b1 + nBase + c);
            const float bg1 = __ldg(b1 + nBase + c + 1);
            #pragma unroll
            for (int i = 0; i < 4; i++)
                #pragma unroll
                for (int hh = 0; hh < 2; hh++) {
                    const int r = rL + i * 16 + hh * 8;
                    const float u0 = us[r * 50 + c];
                    const float u1 = us[r * 50 + c + 1];
                    const float g0 = acc[i][j][2 * hh]     + bg0;
                    const float g1 = acc[i][j][2 * hh + 1] + bg1;
                    const float h0 = g0 * u0 * (1.0f / (1.0f + __expf(-u0)));
                    const float h1 = g1 * u1 * (1.0f / (1.0f + __expf(-u1)));
                    *reinterpret_cast<__half2*>(
                        h + (size_t)(mBase + r) * INTER + nBase + c) =
                        __floats2half2_rn(h0, h1);
                }
        }
    }
}

// ---------------------------------------------------------------------------
// GEMM2: out = h @ W2^T + b2 (fp32). CTA 128x96, 4 warps (2x2), warp 64x48.
// (unchanged from R4)
// ---------------------------------------------------------------------------
__global__ void __launch_bounds__(128, 2)
gemm2(const __half* __restrict__ A, const __half* __restrict__ B,
      const float* __restrict__ bias, float* __restrict__ oF) {
    extern __shared__ __align__(128) char smem[];
    const uint32_t sb0 = smem_u32(smem);
    const int tid = threadIdx.x;
    const int l   = tid & 31;
    const int wid = tid >> 5;
    const int wm  = wid >> 1;
    const int wn  = wid & 1;
    const int mBase = blockIdx.x * BM;
    const int nBase = blockIdx.y * BN;

    auto load_stage = [&](int kt, int slot) {
        const uint32_t sb = sb0 + slot * STAGE;
        const int kc = kt * BK;
        #pragma unroll
        for (int k = 0; k < 8; k++) {                     // A: 1024 chunks
            int idx = tid + k * 128;
            int row = idx >> 3, u = idx & 7;
            cp16(sb + row * 128 + ((u ^ (row & 7)) << 4),
                 A + (size_t)(mBase + row) * HID + kc + u * 8);
        }
        #pragma unroll
        for (int k = 0; k < 6; k++) {                     // B: 768 chunks
            int idx = tid + k * 128;
            int row = idx >> 3, u = idx & 7;
            cp16(sb + OFF_B + row * 128 + ((u ^ (row & 7)) << 4),
                 B + (size_t)(nBase + row) * HID + kc + u * 8);
        }
    };

    const int l7  = l & 7;
    const int lhi = l >> 4;
    const int le  = l & 15;
    const int q   = l >> 3;
    const int aRow0 = wm * 64 + le;
    const int bRowO = wn * 48 + ((q >> 1) << 3) + l7;
    const int bUnit = q & 1;

    auto loadA = [&](uint32_t af[4][4], uint32_t sA, int ks) {
        #pragma unroll
        for (int i = 0; i < 4; i++)
            ldsm4(af[i], sA + (uint32_t)(aRow0 + i * 16) * 128 +
                           (uint32_t)(((ks * 2 + lhi) ^ l7) << 4));
    };
    auto loadB = [&](uint32_t bf[3][4], uint32_t sB, int ks) {
        #pragma unroll
        for (int p = 0; p < 3; p++)
            ldsm4(bf[p], sB + (uint32_t)(bRowO + p * 16) * 128 +
                           (uint32_t)(((ks * 2 + bUnit) ^ l7) << 4));
    };

    float acc[4][6][4] = {};
    uint32_t af[2][4][4], bf[2][3][4];

    #pragma unroll
    for (int s = 0; s < STAGES - 1; s++) {
        load_stage(s, s);
        CP_COMMIT();
    }

    for (int kt = 0; kt < KIT; kt++) {
        CP_WAIT_1();
        __syncthreads();

        const int nk = kt + STAGES - 1;
        if (nk < KIT) load_stage(nk, nk % STAGES);
        CP_COMMIT();

        const uint32_t sA = sb0 + (kt % STAGES) * STAGE;
        const uint32_t sB = sA + OFF_B;

        loadA(af[0], sA, 0);
        loadB(bf[0], sB, 0);
        #pragma unroll
        for (int ks = 0; ks < 4; ks++) {
            const int cur = ks & 1, nxt = cur ^ 1;
            if (ks < 3) {
                loadA(af[nxt], sA, ks + 1);
                loadB(bf[nxt], sB, ks + 1);
            }
            #pragma unroll
            for (int i = 0; i < 4; i++)
                #pragma unroll
                for (int p = 0; p < 3; p++) {
                    mma16816(acc[i][2 * p],     af[cur][i], &bf[cur][p][0]);
                    mma16816(acc[i][2 * p + 1], af[cur][i], &bf[cur][p][2]);
                }
        }
    }

    const int r00 = mBase + wm * 64 + (l >> 2);
    const int cB  = nBase + wn * 48 + 2 * (l & 3);

    #pragma unroll
    for (int i = 0; i < 4; i++)
        #pragma unroll
        for (int j = 0; j < 6; j++) {
            const int c = cB + j * 8;
            const float b0 = __ldg(bias + c), b1v = __ldg(bias + c + 1);
            #pragma unroll
            for (int hh = 0; hh < 2; hh++) {
                const int r = r00 + i * 16 + hh * 8;
                *reinterpret_cast<float2*>(oF + (size_t)r * HID + c) =
                    make_float2(acc[i][j][2 * hh] + b0,
                                acc[i][j][2 * hh + 1] + b1v);
            }
        }
}

// ---------------------------------------------------------------------------
// Host
// ---------------------------------------------------------------------------
extern "C" void kernel_launch(void* const* d_in, const int* in_sizes, int n_in,
                              void* d_out, int out_size) {
    const float* x  = (const float*)d_in[0];   // hidden_states (4096, 2880)
    const float* w1 = (const float*)d_in[3];   // gate_up_w (5760, 2880)
    const float* b1 = (const float*)d_in[4];   // gate_up_b (5760,)
    const float* w2 = (const float*)d_in[5];   // down_w (2880, 2880)
    const float* b2 = (const float*)d_in[6];   // down_b (2880,)
    float* out = (float*)d_out;                // (4096, 2880) fp32

    void *px, *pw1, *pw2, *ph;
    cudaGetSymbolAddress(&px,  g_xh);
    cudaGetSymbolAddress(&pw1, g_w1h);
    cudaGetSymbolAddress(&pw2, g_w2h);
    cudaGetSymbolAddress(&ph,  g_hh);

    // fp32 -> fp16
    {
        int n4 = (SEQ * HID) / 4;
        cvt_kernel<<<(n4 + 255) / 256, 256>>>((const float4*)x,  (uint2*)px,  n4);
        n4 = (NGU * HID) / 4;
        cvt_kernel<<<(n4 + 255) / 256, 256>>>((const float4*)w1, (uint2*)pw1, n4);
        n4 = (HID * INTER) / 4;
        cvt_kernel<<<(n4 + 255) / 256, 256>>>((const float4*)w2, (uint2*)pw2, n4);
    }

    cudaFuncSetAttribute(gemm1_fused,
                         cudaFuncAttributeMaxDynamicSharedMemorySize, SMEM1);
    cudaFuncSetAttribute(gemm2,
                         cudaFuncAttributeMaxDynamicSharedMemorySize, SMEM2);

    // GEMM1 fused: h = (x@Wg^T+bg) * silu(x@Wu^T+bu)   (fp16, 4096 x 2880)
    gemm1_fused<<<dim3(SEQ / BM, INTER / 48), 128, SMEM1>>>(
        (const __half*)px, (const __half*)pw1, b1, (__half*)ph);

    // GEMM2: out = h @ W2^T + b2   (fp32, 4096 x 2880)
    gemm2<<<dim3(SEQ / BM, HID / BN), 128, SMEM2>>>(
        (const __half*)ph, (const __half*)pw2, b2, out);
}

// round 8
// speedup vs baseline: 1.0783x; 1.0502x over previous
#include <cuda_runtime.h>
#include <cuda_fp16.h>
#include <cstdint>

// ============================================================================
// GptOssMoEExperts: router collapses to identity (softmax over top-k sums to 1
// and the expert MLP is shared), so
//   out = ((x@Wg^T+bg) * silu(x@Wu^T+bu)) @ W2^T + b2
// R4 structure (best so far): cvt fp32->fp16, GEMM1 (x@W1^T+b1 -> gateup fp16,
// 5760 cols), standalone SiLU, GEMM2 (h@W2^T+b2 -> fp32).
// R8 change: split the per-kt cp.async convoy (14 LDGSTS at loop head) into 4
// quarters issued inside the ks compute blocks, overlapping LSU issue with
// tensor-pipe issue. Mainloop tile config unchanged (CTA 128x96, warp 64x48,
// 3-stage, 2 CTA/SM).
// ============================================================================

#define SEQ   4096
#define HID   2880
#define INTER 2880
#define NGU   (2 * INTER)   // 5760

static constexpr int BM     = 128;
static constexpr int BN     = 96;
static constexpr int BK     = 64;            // fp16 elems -> 128B rows
static constexpr int KIT    = HID / BK;      // 45
static constexpr int STAGES = 3;
static constexpr int OFF_B  = BM * 128;               // 16384
static constexpr int STAGE  = OFF_B + BN * 128;       // 28672
static constexpr int SMEM_SZ = STAGES * STAGE;        // 86016 (x2 CTA = 172KB/SM)

// ---------------------------------------------------------------------------
// Scratch (__device__ globals = sanctioned allocation-free scratch)
// ---------------------------------------------------------------------------
__device__ __align__(128) __half g_xh [(size_t)SEQ * HID];
__device__ __align__(128) __half g_w1h[(size_t)NGU * HID];
__device__ __align__(128) __half g_w2h[(size_t)HID * INTER];
__device__ __align__(128) __half g_gu [(size_t)SEQ * NGU];
__device__ __align__(128) __half g_hh [(size_t)SEQ * INTER];

// ---------------------------------------------------------------------------
// PTX helpers
// ---------------------------------------------------------------------------
__device__ __forceinline__ uint32_t smem_u32(const void* p) {
    uint32_t a;
    asm("{ .reg .u64 t; cvta.to.shared.u64 t, %1; cvt.u32.u64 %0, t; }" : "=r"(a) : "l"(p));
    return a;
}
__device__ __forceinline__ void ldsm4(uint32_t* r, uint32_t a) {
    asm volatile("ldmatrix.sync.aligned.m8n8.x4.shared.b16 {%0,%1,%2,%3}, [%4];"
                 : "=r"(r[0]), "=r"(r[1]), "=r"(r[2]), "=r"(r[3]) : "r"(a));
}
__device__ __forceinline__ void mma16816(float* d, const uint32_t* a, const uint32_t* b) {
    asm volatile(
        "mma.sync.aligned.m16n8k16.row.col.f32.f16.f16.f32 "
        "{%0,%1,%2,%3}, {%4,%5,%6,%7}, {%8,%9}, {%0,%1,%2,%3};"
        : "+f"(d[0]), "+f"(d[1]), "+f"(d[2]), "+f"(d[3])
        : "r"(a[0]), "r"(a[1]), "r"(a[2]), "r"(a[3]), "r"(b[0]), "r"(b[1]));
}
__device__ __forceinline__ void cp16(uint32_t s, const void* g) {
    asm volatile("cp.async.cg.shared.global [%0], [%1], 16;" :: "r"(s), "l"(g) : "memory");
}
#define CP_COMMIT()  asm volatile("cp.async.commit_group;" ::: "memory")
#define CP_WAIT_1()  asm volatile("cp.async.wait_group 1;"  ::: "memory")

// ---------------------------------------------------------------------------
// fp32 -> fp16 conversion (vectorized)
// ---------------------------------------------------------------------------
__global__ void cvt_kernel(const float4* __restrict__ src, uint2* __restrict__ dst, int n4) {
    int i = blockIdx.x * blockDim.x + threadIdx.x;
    if (i >= n4) return;
    float4 v = src[i];
    __half2 a = __floats2half2_rn(v.x, v.y);
    __half2 b = __floats2half2_rn(v.z, v.w);
    uint2 o;
    o.x = *reinterpret_cast<uint32_t*>(&a);
    o.y = *reinterpret_cast<uint32_t*>(&b);
    dst[i] = o;
}

// ---------------------------------------------------------------------------
// Elementwise SiLU-mul: h[r,c] = gu[r,c] * silu(gu[r,INTER+c]), 8 elems/thread
// ---------------------------------------------------------------------------
__global__ void silu_kernel(const __half* __restrict__ gu, __half* __restrict__ h) {
    const int i = blockIdx.x * blockDim.x + threadIdx.x;
    const int n8 = SEQ * INTER / 8;
    if (i >= n8) return;
    const int r  = i / (INTER / 8);
    const int c8 = i % (INTER / 8);
    const uint4 gv = *reinterpret_cast<const uint4*>(gu + (size_t)r * NGU + c8 * 8);
    const uint4 uv = *reinterpret_cast<const uint4*>(gu + (size_t)r * NGU + INTER + c8 * 8);
    const __half2* gp = reinterpret_cast<const __half2*>(&gv);
    const __half2* up = reinterpret_cast<const __half2*>(&uv);
    uint4 ov;
    __half2* op = reinterpret_cast<__half2*>(&ov);
    #pragma unroll
    for (int k = 0; k < 4; k++) {
        float2 g = __half22float2(gp[k]);
        float2 u = __half22float2(up[k]);
        float h0 = g.x * u.x * (1.0f / (1.0f + __expf(-u.x)));
        float h1 = g.y * u.y * (1.0f / (1.0f + __expf(-u.y)));
        op[k] = __floats2half2_rn(h0, h1);
    }
    *reinterpret_cast<uint4*>(h + (size_t)r * INTER + c8 * 8) = ov;
}

// ---------------------------------------------------------------------------
// Pipelined fp16 GEMM:  C[BM x BN] = A[BM x K] * B[BN x K]^T + bias
//   HALF_OUT=true : store fp16 (gateup buffer), false: fp32 (final out)
// 128 threads = 4 warps (2M x 2N); warp tile 64 x 48.
// Smem rows 128B, 16B units XOR-swizzled by (row&7). Register double-buffered
// fragments, 3-stage cp.async, 2 CTAs/SM. Next-stage LDGSTS issue is split
// into 4 quarters, one per ks compute block (overlaps LSU with tensor issue).
// ---------------------------------------------------------------------------
template <bool HALF_OUT>
__global__ void __launch_bounds__(128, 2)
gemm_f16(const __half* __restrict__ A, const __half* __restrict__ B,
         const float* __restrict__ bias,
         __half* __restrict__ oH, float* __restrict__ oF, int ldo) {
    extern __shared__ __align__(128) char smem[];
    const uint32_t sb0 = smem_u32(smem);
    const int tid = threadIdx.x;
    const int l   = tid & 31;
    const int wid = tid >> 5;          // 0..3
    const int wm  = wid >> 1;          // 0..1
    const int wn  = wid & 1;           // 0..1
    const int mBase = blockIdx.x * BM;
    const int nBase = blockIdx.y * BN;

    // One quarter of a stage's loads: 2 A chunks + (2|1) B chunks per thread.
    auto load_part = [&](int kt, int slot, int part) {
        const uint32_t sb = sb0 + slot * STAGE;
        const int kc = kt * BK;
        #pragma unroll
        for (int k = 2 * part; k < 2 * part + 2; k++) {       // A chunks
            int idx = tid + k * 128;
            int row = idx >> 3, u = idx & 7;
            cp16(sb + row * 128 + ((u ^ (row & 7)) << 4),
                 A + (size_t)(mBase + row) * HID + kc + u * 8);
        }
        if (part < 2) {                                       // B chunks 0-3
            #pragma unroll
            for (int k = 2 * part; k < 2 * part + 2; k++) {
                int idx = tid + k * 128;
                int row = idx >> 3, u = idx & 7;
                cp16(sb + OFF_B + row * 128 + ((u ^ (row & 7)) << 4),
                     B + (size_t)(nBase + row) * HID + kc + u * 8);
            }
        } else {                                              // B chunks 4-5
            int idx = tid + (part + 2) * 128;
            int row = idx >> 3, u = idx & 7;
            cp16(sb + OFF_B + row * 128 + ((u ^ (row & 7)) << 4),
                 B + (size_t)(nBase + row) * HID + kc + u * 8);
        }
    };
    auto load_stage = [&](int kt, int slot) {
        #pragma unroll
        for (int p = 0; p < 4; p++) load_part(kt, slot, p);
    };

    const int l7  = l & 7;
    const int lhi = l >> 4;
    const int le  = l & 15;
    const int q   = l >> 3;
    const int aRow0 = wm * 64 + le;
    const int bRowO = wn * 48 + ((q >> 1) << 3) + l7;
    const int bUnit = q & 1;

    auto loadA = [&](uint32_t af[4][4], uint32_t sA, int ks) {
        #pragma unroll
        for (int i = 0; i < 4; i++)
            ldsm4(af[i], sA + (uint32_t)(aRow0 + i * 16) * 128 +
                           (uint32_t)(((ks * 2 + lhi) ^ l7) << 4));
    };
    auto loadB = [&](uint32_t bf[3][4], uint32_t sB, int ks) {
        #pragma unroll
        for (int p = 0; p < 3; p++)
            ldsm4(bf[p], sB + (uint32_t)(bRowO + p * 16) * 128 +
                           (uint32_t)(((ks * 2 + bUnit) ^ l7) << 4));
    };

    float acc[4][6][4] = {};
    uint32_t af[2][4][4], bf[2][3][4];

    #pragma unroll
    for (int s = 0; s < STAGES - 1; s++) {                // prologue
        load_stage(s, s);
        CP_COMMIT();
    }

    for (int kt = 0; kt < KIT; kt++) {
        CP_WAIT_1();
        __syncthreads();

        const int  nk     = kt + STAGES - 1;
        const bool doLoad = nk < KIT;
        const int  slot   = nk % STAGES;

        const uint32_t sA = sb0 + (kt % STAGES) * STAGE;
        const uint32_t sB = sA + OFF_B;

        loadA(af[0], sA, 0);
        loadB(bf[0], sB, 0);
        #pragma unroll
        for (int ks = 0; ks < 4; ks++) {
            const int cur = ks & 1, nxt = cur ^ 1;
            if (ks < 3) {
                loadA(af[nxt], sA, ks + 1);
                loadB(bf[nxt], sB, ks + 1);
            }
            if (doLoad) load_part(nk, slot, ks);          // interleaved quarter
            #pragma unroll
            for (int i = 0; i < 4; i++)
                #pragma unroll
                for (int p = 0; p < 3; p++) {
                    mma16816(acc[i][2 * p],     af[cur][i], &bf[cur][p][0]);
                    mma16816(acc[i][2 * p + 1], af[cur][i], &bf[cur][p][2]);
                }
        }
        CP_COMMIT();
    }

    // ------------------------------- epilogue -------------------------------
    const int r00 = mBase + wm * 64 + (l >> 2);
    const int cB  = nBase + wn * 48 + 2 * (l & 3);

    #pragma unroll
    for (int i = 0; i < 4; i++)
        #pragma unroll
        for (int j = 0; j < 6; j++) {
            const int c = cB + j * 8;
            const float b0 = __ldg(bias + c), b1 = __ldg(bias + c + 1);
            #pragma unroll
            for (int hh = 0; hh < 2; hh++) {
                const int r = r00 + i * 16 + hh * 8;
                const float v0 = acc[i][j][2 * hh]     + b0;
                const float v1 = acc[i][j][2 * hh + 1] + b1;
                if constexpr (HALF_OUT) {
                    *reinterpret_cast<__half2*>(oH + (size_t)r * ldo + c) =
                        __floats2half2_rn(v0, v1);
                } else {
                    *reinterpret_cast<float2*>(oF + (size_t)r * ldo + c) =
                        make_float2(v0, v1);
                }
            }
        }
}

// ---------------------------------------------------------------------------
// Host
// ---------------------------------------------------------------------------
extern "C" void kernel_launch(void* const* d_in, const int* in_sizes, int n_in,
                              void* d_out, int out_size) {
    const float* x  = (const float*)d_in[0];   // hidden_states (4096, 2880)
    const float* w1 = (const float*)d_in[3];   // gate_up_w (5760, 2880)
    const float* b1 = (const float*)d_in[4];   // gate_up_b (5760,)
    const float* w2 = (const float*)d_in[5];   // down_w (2880, 2880)
    const float* b2 = (const float*)d_in[6];   // down_b (2880,)
    float* out = (float*)d_out;                // (4096, 2880) fp32

    void *px, *pw1, *pw2, *pgu, *ph;
    cudaGetSymbolAddress(&px,  g_xh);
    cudaGetSymbolAddress(&pw1, g_w1h);
    cudaGetSymbolAddress(&pw2, g_w2h);
    cudaGetSymbolAddress(&pgu, g_gu);
    cudaGetSymbolAddress(&ph,  g_hh);

    // fp32 -> fp16
    {
        int n4 = (SEQ * HID) / 4;
        cvt_kernel<<<(n4 + 255) / 256, 256>>>((const float4*)x,  (uint2*)px,  n4);
        n4 = (NGU * HID) / 4;
        cvt_kernel<<<(n4 + 255) / 256, 256>>>((const float4*)w1, (uint2*)pw1, n4);
        n4 = (HID * INTER) / 4;
        cvt_kernel<<<(n4 + 255) / 256, 256>>>((const float4*)w2, (uint2*)pw2, n4);
    }

    cudaFuncSetAttribute(gemm_f16<true>,
                         cudaFuncAttributeMaxDynamicSharedMemorySize, SMEM_SZ);
    cudaFuncSetAttribute(gemm_f16<false>,
                         cudaFuncAttributeMaxDynamicSharedMemorySize, SMEM_SZ);

    // GEMM1: gateup = x @ W1^T + b1   (fp16, 4096 x 5760)
    gemm_f16<true><<<dim3(SEQ / BM, NGU / BN), 128, SMEM_SZ>>>(
        (const __half*)px, (const __half*)pw1, b1, (__half*)pgu, nullptr, NGU);

    // SiLU: h = gate * silu(up)   (fp16, 4096 x 2880)
    {
        int n8 = SEQ * INTER / 8;
        silu_kernel<<<(n8 + 255) / 256, 256>>>((const __half*)pgu, (__half*)ph);
    }

    // GEMM2: out = h @ W2^T + b2   (fp32, 4096 x 2880)
    gemm_f16<false><<<dim3(SEQ / BM, INTER / BN), 128, SMEM_SZ>>>(
        (const __half*)ph, (const __half*)pw2, b2, nullptr, out, HID);
}

// round 9
// speedup vs baseline: 1.1719x; 1.0868x over previous
#include <cuda_runtime.h>
#include <cuda_fp16.h>
#include <cstdint>

// ============================================================================
// GptOssMoEExperts: router collapses to identity (softmax over top-k sums to 1
// and the expert MLP is shared), so
//   out = ((x@Wg^T+bg) * silu(x@Wu^T+bu)) @ W2^T + b2
// Structure: cvt fp32->fp16, GEMM1 (x@W1^T+b1 -> gateup fp16), SiLU, GEMM2.
// R9 change: 4-stage cp.async pipeline (112KB/CTA, 2 CTA/SM) + cross-kt
// fragment prefetch — at ks=3 of tile kt the register double-buffer loads the
// ks=0 fragments of tile kt+1 (stage kt+1 is guaranteed resident under
// wait_group 1 with 4 stages), eliminating the kt-head ldmatrix bubble.
// LDGSTS still interleaved as quarters inside the ks blocks (R8 win).
// ============================================================================

#define SEQ   4096
#define HID   2880
#define INTER 2880
#define NGU   (2 * INTER)   // 5760

static constexpr int BM     = 128;
static constexpr int BN     = 96;
static constexpr int BK     = 64;            // fp16 elems -> 128B rows
static constexpr int KIT    = HID / BK;      // 45
static constexpr int STAGES = 4;
static constexpr int OFF_B  = BM * 128;               // 16384
static constexpr int STAGE  = OFF_B + BN * 128;       // 28672
static constexpr int SMEM_SZ = STAGES * STAGE;        // 114688 = 112KB (x2 = 224KB/SM)

// ---------------------------------------------------------------------------
// Scratch (__device__ globals = sanctioned allocation-free scratch)
// ---------------------------------------------------------------------------
__device__ __align__(128) __half g_xh [(size_t)SEQ * HID];
__device__ __align__(128) __half g_w1h[(size_t)NGU * HID];
__device__ __align__(128) __half g_w2h[(size_t)HID * INTER];
__device__ __align__(128) __half g_gu [(size_t)SEQ * NGU];
__device__ __align__(128) __half g_hh [(size_t)SEQ * INTER];

// ---------------------------------------------------------------------------
// PTX helpers
// ---------------------------------------------------------------------------
__device__ __forceinline__ uint32_t smem_u32(const void* p) {
    uint32_t a;
    asm("{ .reg .u64 t; cvta.to.shared.u64 t, %1; cvt.u32.u64 %0, t; }" : "=r"(a) : "l"(p));
    return a;
}
__device__ __forceinline__ void ldsm4(uint32_t* r, uint32_t a) {
    asm volatile("ldmatrix.sync.aligned.m8n8.x4.shared.b16 {%0,%1,%2,%3}, [%4];"
                 : "=r"(r[0]), "=r"(r[1]), "=r"(r[2]), "=r"(r[3]) : "r"(a));
}
__device__ __forceinline__ void mma16816(float* d, const uint32_t* a, const uint32_t* b) {
    asm volatile(
        "mma.sync.aligned.m16n8k16.row.col.f32.f16.f16.f32 "
        "{%0,%1,%2,%3}, {%4,%5,%6,%7}, {%8,%9}, {%0,%1,%2,%3};"
        : "+f"(d[0]), "+f"(d[1]), "+f"(d[2]), "+f"(d[3])
        : "r"(a[0]), "r"(a[1]), "r"(a[2]), "r"(a[3]), "r"(b[0]), "r"(b[1]));
}
__device__ __forceinline__ void cp16(uint32_t s, const void* g) {
    asm volatile("cp.async.cg.shared.global [%0], [%1], 16;" :: "r"(s), "l"(g) : "memory");
}
#define CP_COMMIT()  asm volatile("cp.async.commit_group;" ::: "memory")
#define CP_WAIT_1()  asm volatile("cp.async.wait_group 1;"  ::: "memory")

// ---------------------------------------------------------------------------
// fp32 -> fp16 conversion (vectorized)
// ---------------------------------------------------------------------------
__global__ void cvt_kernel(const float4* __restrict__ src, uint2* __restrict__ dst, int n4) {
    int i = blockIdx.x * blockDim.x + threadIdx.x;
    if (i >= n4) return;
    float4 v = src[i];
    __half2 a = __floats2half2_rn(v.x, v.y);
    __half2 b = __floats2half2_rn(v.z, v.w);
    uint2 o;
    o.x = *reinterpret_cast<uint32_t*>(&a);
    o.y = *reinterpret_cast<uint32_t*>(&b);
    dst[i] = o;
}

// ---------------------------------------------------------------------------
// Elementwise SiLU-mul: h[r,c] = gu[r,c] * silu(gu[r,INTER+c]), 8 elems/thread
// ---------------------------------------------------------------------------
__global__ void silu_kernel(const __half* __restrict__ gu, __half* __restrict__ h) {
    const int i = blockIdx.x * blockDim.x + threadIdx.x;
    const int n8 = SEQ * INTER / 8;
    if (i >= n8) return;
    const int r  = i / (INTER / 8);
    const int c8 = i % (INTER / 8);
    const uint4 gv = *reinterpret_cast<const uint4*>(gu + (size_t)r * NGU + c8 * 8);
    const uint4 uv = *reinterpret_cast<const uint4*>(gu + (size_t)r * NGU + INTER + c8 * 8);
    const __half2* gp = reinterpret_cast<const __half2*>(&gv);
    const __half2* up = reinterpret_cast<const __half2*>(&uv);
    uint4 ov;
    __half2* op = reinterpret_cast<__half2*>(&ov);
    #pragma unroll
    for (int k = 0; k < 4; k++) {
        float2 g = __half22float2(gp[k]);
        float2 u = __half22float2(up[k]);
        float h0 = g.x * u.x * (1.0f / (1.0f + __expf(-u.x)));
        float h1 = g.y * u.y * (1.0f / (1.0f + __expf(-u.y)));
        op[k] = __floats2half2_rn(h0, h1);
    }
    *reinterpret_cast<uint4*>(h + (size_t)r * INTER + c8 * 8) = ov;
}

// ---------------------------------------------------------------------------
// Pipelined fp16 GEMM:  C[BM x BN] = A[BM x K] * B[BN x K]^T + bias
//   HALF_OUT=true : store fp16 (gateup buffer), false: fp32 (final out)
// 128 threads = 4 warps (2M x 2N); warp tile 64 x 48.
// 4-stage cp.async, wait_group 1 (stages kt and kt+1 resident at each tile),
// cross-kt register-fragment prefetch, LDGSTS interleaved per ks, 2 CTAs/SM.
// ---------------------------------------------------------------------------
template <bool HALF_OUT>
__global__ void __launch_bounds__(128, 2)
gemm_f16(const __half* __restrict__ A, const __half* __restrict__ B,
         const float* __restrict__ bias,
         __half* __restrict__ oH, float* __restrict__ oF, int ldo) {
    extern __shared__ __align__(128) char smem[];
    const uint32_t sb0 = smem_u32(smem);
    const int tid = threadIdx.x;
    const int l   = tid & 31;
    const int wid = tid >> 5;          // 0..3
    const int wm  = wid >> 1;          // 0..1
    const int wn  = wid & 1;           // 0..1
    const int mBase = blockIdx.x * BM;
    const int nBase = blockIdx.y * BN;

    // One quarter of a stage's loads: 2 A chunks + (2|1) B chunks per thread.
    auto load_part = [&](int kt, int slot, int part) {
        const uint32_t sb = sb0 + slot * STAGE;
        const int kc = kt * BK;
        #pragma unroll
        for (int k = 2 * part; k < 2 * part + 2; k++) {       // A chunks
            int idx = tid + k * 128;
            int row = idx >> 3, u = idx & 7;
            cp16(sb + row * 128 + ((u ^ (row & 7)) << 4),
                 A + (size_t)(mBase + row) * HID + kc + u * 8);
        }
        if (part < 2) {                                       // B chunks 0-3
            #pragma unroll
            for (int k = 2 * part; k < 2 * part + 2; k++) {
                int idx = tid + k * 128;
                int row = idx >> 3, u = idx & 7;
                cp16(sb + OFF_B + row * 128 + ((u ^ (row & 7)) << 4),
                     B + (size_t)(nBase + row) * HID + kc + u * 8);
            }
        } else {                                              // B chunks 4-5
            int idx = tid + (part + 2) * 128;
            int row = idx >> 3, u = idx & 7;
            cp16(sb + OFF_B + row * 128 + ((u ^ (row & 7)) << 4),
                 B + (size_t)(nBase + row) * HID + kc + u * 8);
        }
    };
    auto load_stage = [&](int kt, int slot) {
        #pragma unroll
        for (int p = 0; p < 4; p++) load_part(kt, slot, p);
    };

    const int l7  = l & 7;
    const int lhi = l >> 4;
    const int le  = l & 15;
    const int q   = l >> 3;
    const int aRow0 = wm * 64 + le;
    const int bRowO = wn * 48 + ((q >> 1) << 3) + l7;
    const int bUnit = q & 1;

    auto loadA = [&](uint32_t af[4][4], uint32_t sA, int ks) {
        #pragma unroll
        for (int i = 0; i < 4; i++)
            ldsm4(af[i], sA + (uint32_t)(aRow0 + i * 16) * 128 +
                           (uint32_t)(((ks * 2 + lhi) ^ l7) << 4));
    };
    auto loadB = [&](uint32_t bf[3][4], uint32_t sB, int ks) {
        #pragma unroll
        for (int p = 0; p < 3; p++)
            ldsm4(bf[p], sB + (uint32_t)(bRowO + p * 16) * 128 +
                           (uint32_t)(((ks * 2 + bUnit) ^ l7) << 4));
    };

    float acc[4][6][4] = {};
    uint32_t af[2][4][4], bf[2][3][4];

    #pragma unroll
    for (int s = 0; s < STAGES - 1; s++) {                // prologue: 3 stages
        load_stage(s, s);
        CP_COMMIT();
    }

    // Peeled head: stages 0 and 1 resident after this wait.
    CP_WAIT_1();
    __syncthreads();
    loadA(af[0], sb0, 0);
    loadB(bf[0], sb0 + OFF_B, 0);

    for (int kt = 0; kt < KIT; kt++) {
        const int  nk     = kt + STAGES - 1;
        const bool doLoad = nk < KIT;
        const int  slot   = nk % STAGES;

        const uint32_t sA  = sb0 + (kt % STAGES) * STAGE;
        const uint32_t sB  = sA + OFF_B;
        const uint32_t sAn = sb0 + ((kt + 1) % STAGES) * STAGE;   // next tile
        const uint32_t sBn = sAn + OFF_B;

        #pragma unroll
        for (int ks = 0; ks < 4; ks++) {
            const int cur = ks & 1, nxt = cur ^ 1;
            if (ks < 3) {
                loadA(af[nxt], sA, ks + 1);
                loadB(bf[nxt], sB, ks + 1);
            } else if (kt + 1 < KIT) {
                loadA(af[nxt], sAn, 0);       // cross-kt prefetch (stage kt+1
                loadB(bf[nxt], sBn, 0);       //  resident under 4-stage WAIT_1)
            }
            if (doLoad) load_part(nk, slot, ks);
            #pragma unroll
            for (int i = 0; i < 4; i++)
                #pragma unroll
                for (int p = 0; p < 3; p++) {
                    mma16816(acc[i][2 * p],     af[cur][i], &bf[cur][p][0]);
                    mma16816(acc[i][2 * p + 1], af[cur][i], &bf[cur][p][2]);
                }
        }
        CP_COMMIT();
        if (kt + 1 < KIT) {
            CP_WAIT_1();          // stages kt+1, kt+2 resident after this
            __syncthreads();      // protect slot (kt+4)%4 = kt%4 reuse
        }
    }

    // ------------------------------- epilogue -------------------------------
    const int r00 = mBase + wm * 64 + (l >> 2);
    const int cB  = nBase + wn * 48 + 2 * (l & 3);

    #pragma unroll
    for (int i = 0; i < 4; i++)
        #pragma unroll
        for (int j = 0; j < 6; j++) {
            const int c = cB + j * 8;
            const float b0 = __ldg(bias + c), b1 = __ldg(bias + c + 1);
            #pragma unroll
            for (int hh = 0; hh < 2; hh++) {
                const int r = r00 + i * 16 + hh * 8;
                const float v0 = acc[i][j][2 * hh]     + b0;
                const float v1 = acc[i][j][2 * hh + 1] + b1;
                if constexpr (HALF_OUT) {
                    *reinterpret_cast<__half2*>(oH + (size_t)r * ldo + c) =
                        __floats2half2_rn(v0, v1);
                } else {
                    *reinterpret_cast<float2*>(oF + (size_t)r * ldo + c) =
                        make_float2(v0, v1);
                }
            }
        }
}

// ---------------------------------------------------------------------------
// Host
// ---------------------------------------------------------------------------
extern "C" void kernel_launch(void* const* d_in, const int* in_sizes, int n_in,
                              void* d_out, int out_size) {
    const float* x  = (const float*)d_in[0];   // hidden_states (4096, 2880)
    const float* w1 = (const float*)d_in[3];   // gate_up_w (5760, 2880)
    const float* b1 = (const float*)d_in[4];   // gate_up_b (5760,)
    const float* w2 = (const float*)d_in[5];   // down_w (2880, 2880)
    const float* b2 = (const float*)d_in[6];   // down_b (2880,)
    float* out = (float*)d_out;                // (4096, 2880) fp32

    void *px, *pw1, *pw2, *pgu, *ph;
    cudaGetSymbolAddress(&px,  g_xh);
    cudaGetSymbolAddress(&pw1, g_w1h);
    cudaGetSymbolAddress(&pw2, g_w2h);
    cudaGetSymbolAddress(&pgu, g_gu);
    cudaGetSymbolAddress(&ph,  g_hh);

    // fp32 -> fp16
    {
        int n4 = (SEQ * HID) / 4;
        cvt_kernel<<<(n4 + 255) / 256, 256>>>((const float4*)x,  (uint2*)px,  n4);
        n4 = (NGU * HID) / 4;
        cvt_kernel<<<(n4 + 255) / 256, 256>>>((const float4*)w1, (uint2*)pw1, n4);
        n4 = (HID * INTER) / 4;
        cvt_kernel<<<(n4 + 255) / 256, 256>>>((const float4*)w2, (uint2*)pw2, n4);
    }

    cudaFuncSetAttribute(gemm_f16<true>,
                         cudaFuncAttributeMaxDynamicSharedMemorySize, SMEM_SZ);
    cudaFuncSetAttribute(gemm_f16<false>,
                         cudaFuncAttributeMaxDynamicSharedMemorySize, SMEM_SZ);

    // GEMM1: gateup = x @ W1^T + b1   (fp16, 4096 x 5760)
    gemm_f16<true><<<dim3(SEQ / BM, NGU / BN), 128, SMEM_SZ>>>(
        (const __half*)px, (const __half*)pw1, b1, (__half*)pgu, nullptr, NGU);

    // SiLU: h = gate * silu(up)   (fp16, 4096 x 2880)
    {
        int n8 = SEQ * INTER / 8;
        silu_kernel<<<(n8 + 255) / 256, 256>>>((const __half*)pgu, (__half*)ph);
    }

    // GEMM2: out = h @ W2^T + b2   (fp32, 4096 x 2880)
    gemm_f16<false><<<dim3(SEQ / BM, INTER / BN), 128, SMEM_SZ>>>(
        (const __half*)ph, (const __half*)pw2, b2, nullptr, out, HID);
}

// round 10
// speedup vs baseline: 1.1784x; 1.0056x over previous
#include <cuda_runtime.h>
#include <cuda_fp16.h>
#include <cstdint>

// ============================================================================
// GptOssMoEExperts: router collapses to identity (softmax over top-k sums to 1
// and the expert MLP is shared), so
//   out = ((x@Wg^T+bg) * silu(x@Wu^T+bu)) @ W2^T + b2
// Structure: cvt fp32->fp16, GEMM1 (x@W1^T+b1 -> gateup fp16), SiLU, GEMM2.
// R9 base: 4-stage cp.async (112KB/CTA, 2 CTA/SM), cross-kt fragment prefetch,
// LDGSTS quarters interleaved into ks blocks. tensor=80%.
// R10 change: strength-reduced cp.async addressing. Per-thread global pointers
// advance by BK per tile; smem offsets are chunk-invariant under the swizzle
// ((row+16k)&7 == row&7), so every cp16 address is base + constant. Cuts the
// per-kt IMAD convoys (alu was 8.3% of peak, stealing issue slots from HMMA).
// ============================================================================

#define SEQ   4096
#define HID   2880
#define INTER 2880
#define NGU   (2 * INTER)   // 5760

static constexpr int BM     = 128;
static constexpr int BN     = 96;
static constexpr int BK     = 64;            // fp16 elems -> 128B rows
static constexpr int KIT    = HID / BK;      // 45
static constexpr int STAGES = 4;
static constexpr int OFF_B  = BM * 128;               // 16384
static constexpr int STAGE  = OFF_B + BN * 128;       // 28672
static constexpr int SMEM_SZ = STAGES * STAGE;        // 114688 (x2 = 224KB/SM)

// ---------------------------------------------------------------------------
// Scratch (__device__ globals = sanctioned allocation-free scratch)
// ---------------------------------------------------------------------------
__device__ __align__(128) __half g_xh [(size_t)SEQ * HID];
__device__ __align__(128) __half g_w1h[(size_t)NGU * HID];
__device__ __align__(128) __half g_w2h[(size_t)HID * INTER];
__device__ __align__(128) __half g_gu [(size_t)SEQ * NGU];
__device__ __align__(128) __half g_hh [(size_t)SEQ * INTER];

// ---------------------------------------------------------------------------
// PTX helpers
// ---------------------------------------------------------------------------
__device__ __forceinline__ uint32_t smem_u32(const void* p) {
    uint32_t a;
    asm("{ .reg .u64 t; cvta.to.shared.u64 t, %1; cvt.u32.u64 %0, t; }" : "=r"(a) : "l"(p));
    return a;
}
__device__ __forceinline__ void ldsm4(uint32_t* r, uint32_t a) {
    asm volatile("ldmatrix.sync.aligned.m8n8.x4.shared.b16 {%0,%1,%2,%3}, [%4];"
                 : "=r"(r[0]), "=r"(r[1]), "=r"(r[2]), "=r"(r[3]) : "r"(a));
}
__device__ __forceinline__ void mma16816(float* d, const uint32_t* a, const uint32_t* b) {
    asm volatile(
        "mma.sync.aligned.m16n8k16.row.col.f32.f16.f16.f32 "
        "{%0,%1,%2,%3}, {%4,%5,%6,%7}, {%8,%9}, {%0,%1,%2,%3};"
        : "+f"(d[0]), "+f"(d[1]), "+f"(d[2]), "+f"(d[3])
        : "r"(a[0]), "r"(a[1]), "r"(a[2]), "r"(a[3]), "r"(b[0]), "r"(b[1]));
}
__device__ __forceinline__ void cp16(uint32_t s, const void* g) {
    asm volatile("cp.async.cg.shared.global [%0], [%1], 16;" :: "r"(s), "l"(g) : "memory");
}
#define CP_COMMIT()  asm volatile("cp.async.commit_group;" ::: "memory")
#define CP_WAIT_1()  asm volatile("cp.async.wait_group 1;"  ::: "memory")

// ---------------------------------------------------------------------------
// fp32 -> fp16 conversion (vectorized)
// ---------------------------------------------------------------------------
__global__ void cvt_kernel(const float4* __restrict__ src, uint2* __restrict__ dst, int n4) {
    int i = blockIdx.x * blockDim.x + threadIdx.x;
    if (i >= n4) return;
    float4 v = src[i];
    __half2 a = __floats2half2_rn(v.x, v.y);
    __half2 b = __floats2half2_rn(v.z, v.w);
    uint2 o;
    o.x = *reinterpret_cast<uint32_t*>(&a);
    o.y = *reinterpret_cast<uint32_t*>(&b);
    dst[i] = o;
}

// ---------------------------------------------------------------------------
// Elementwise SiLU-mul: h[r,c] = gu[r,c] * silu(gu[r,INTER+c]), 8 elems/thread
// ---------------------------------------------------------------------------
__global__ void silu_kernel(const __half* __restrict__ gu, __half* __restrict__ h) {
    const int i = blockIdx.x * blockDim.x + threadIdx.x;
    const int n8 = SEQ * INTER / 8;
    if (i >= n8) return;
    const int r  = i / (INTER / 8);
    const int c8 = i % (INTER / 8);
    const uint4 gv = *reinterpret_cast<const uint4*>(gu + (size_t)r * NGU + c8 * 8);
    const uint4 uv = *reinterpret_cast<const uint4*>(gu + (size_t)r * NGU + INTER + c8 * 8);
    const __half2* gp = reinterpret_cast<const __half2*>(&gv);
    const __half2* up = reinterpret_cast<const __half2*>(&uv);
    uint4 ov;
    __half2* op = reinterpret_cast<__half2*>(&ov);
    #pragma unroll
    for (int k = 0; k < 4; k++) {
        float2 g = __half22float2(gp[k]);
        float2 u = __half22float2(up[k]);
        float h0 = g.x * u.x * (1.0f / (1.0f + __expf(-u.x)));
        float h1 = g.y * u.y * (1.0f / (1.0f + __expf(-u.y)));
        op[k] = __floats2half2_rn(h0, h1);
    }
    *reinterpret_cast<uint4*>(h + (size_t)r * INTER + c8 * 8) = ov;
}

// ---------------------------------------------------------------------------
// Pipelined fp16 GEMM:  C[BM x BN] = A[BM x K] * B[BN x K]^T + bias
//   HALF_OUT=true : store fp16 (gateup buffer), false: fp32 (final out)
// 128 threads = 4 warps (2M x 2N); warp tile 64 x 48.
// 4-stage cp.async, wait_group 1, cross-kt register-fragment prefetch,
// LDGSTS interleaved per ks with strength-reduced addressing, 2 CTAs/SM.
// ---------------------------------------------------------------------------
template <bool HALF_OUT>
__global__ void __launch_bounds__(128, 2)
gemm_f16(const __half* __restrict__ A, const __half* __restrict__ B,
         const float* __restrict__ bias,
         __half* __restrict__ oH, float* __restrict__ oF, int ldo) {
    extern __shared__ __align__(128) char smem[];
    const uint32_t sb0 = smem_u32(smem);
    const int tid = threadIdx.x;
    const int l   = tid & 31;
    const int wid = tid >> 5;          // 0..3
    const int wm  = wid >> 1;          // 0..1
    const int wn  = wid & 1;           // 0..1
    const int mBase = blockIdx.x * BM;
    const int nBase = blockIdx.y * BN;

    // ---- strength-reduced cp.async addressing ----
    // chunk k covers row rowT+16k; (rowT+16k)&7 == rowT&7, so the swizzled
    // smem offset is base + k*2048 and the global addr is base + k*16*HID.
    const int rowT = tid >> 3;                    // 0..15
    const int u8   = tid & 7;
    const uint32_t aSmem = (uint32_t)rowT * 128 + (uint32_t)((u8 ^ (rowT & 7)) << 4);
    const uint32_t bSmem = OFF_B + aSmem;
    const __half* gAn = A + (size_t)(mBase + rowT) * HID + u8 * 8;  // next tile to load
    const __half* gBn = B + (size_t)(nBase + rowT) * HID + u8 * 8;

    // One quarter of a stage's loads: 2 A chunks + (2|1) B chunks per thread.
    auto load_part = [&](uint32_t sbSlot, int part) {
        #pragma unroll
        for (int k = 2 * part; k < 2 * part + 2; k++)         // A chunks
            cp16(sbSlot + aSmem + k * 2048, gAn + (size_t)k * 16 * HID);
        if (part < 2) {                                       // B chunks 0-3
            #pragma unroll
            for (int k = 2 * part; k < 2 * part + 2; k++)
                cp16(sbSlot + bSmem + k * 2048, gBn + (size_t)k * 16 * HID);
        } else {                                              // B chunks 4-5
            const int k = part + 2;
            cp16(sbSlot + bSmem + k * 2048, gBn + (size_t)k * 16 * HID);
        }
    };

    const int l7  = l & 7;
    const int lhi = l >> 4;
    const int le  = l & 15;
    const int q   = l >> 3;
    const int aRow0 = wm * 64 + le;
    const int bRowO = wn * 48 + ((q >> 1) << 3) + l7;
    const int bUnit = q & 1;

    auto loadA = [&](uint32_t af[4][4], uint32_t sA, int ks) {
        #pragma unroll
        for (int i = 0; i < 4; i++)
            ldsm4(af[i], sA + (uint32_t)(aRow0 + i * 16) * 128 +
                           (uint32_t)(((ks * 2 + lhi) ^ l7) << 4));
    };
    auto loadB = [&](uint32_t bf[3][4], uint32_t sB, int ks) {
        #pragma unroll
        for (int p = 0; p < 3; p++)
            ldsm4(bf[p], sB + (uint32_t)(bRowO + p * 16) * 128 +
                           (uint32_t)(((ks * 2 + bUnit) ^ l7) << 4));
    };

    float acc[4][6][4] = {};
    uint32_t af[2][4][4], bf[2][3][4];

    #pragma unroll
    for (int s = 0; s < STAGES - 1; s++) {                // prologue: 3 stages
        const uint32_t sbSlot = sb0 + s * STAGE;
        #pragma unroll
        for (int p = 0; p < 4; p++) load_part(sbSlot, p);
        CP_COMMIT();
        gAn += BK;  gBn += BK;
    }

    // Peeled head: stages 0 and 1 resident after this wait.
    CP_WAIT_1();
    __syncthreads();
    loadA(af[0], sb0, 0);
    loadB(bf[0], sb0 + OFF_B, 0);

    for (int kt = 0; kt < KIT; kt++) {
        const int  nk     = kt + STAGES - 1;
        const bool doLoad = nk < KIT;
        const uint32_t sbSlot = sb0 + (nk % STAGES) * STAGE;

        const uint32_t sA  = sb0 + (kt % STAGES) * STAGE;
        const uint32_t sB  = sA + OFF_B;
        const uint32_t sAn = sb0 + ((kt + 1) % STAGES) * STAGE;   // next tile
        const uint32_t sBn = sAn + OFF_B;

        #pragma unroll
        for (int ks = 0; ks < 4; ks++) {
            const int cur = ks & 1, nxt = cur ^ 1;
            if (ks < 3) {
                loadA(af[nxt], sA, ks + 1);
                loadB(bf[nxt], sB, ks + 1);
            } else if (kt + 1 < KIT) {
                loadA(af[nxt], sAn, 0);       // cross-kt prefetch (stage kt+1
                loadB(bf[nxt], sBn, 0);       //  resident under 4-stage WAIT_1)
            }
            if (doLoad) load_part(sbSlot, ks);
            #pragma unroll
            for (int i = 0; i < 4; i++)
                #pragma unroll
                for (int p = 0; p < 3; p++) {
                    mma16816(acc[i][2 * p],     af[cur][i], &bf[cur][p][0]);
                    mma16816(acc[i][2 * p + 1], af[cur][i], &bf[cur][p][2]);
                }
        }
        CP_COMMIT();
        gAn += BK;  gBn += BK;
        if (kt + 1 < KIT) {
            CP_WAIT_1();          // stages kt+1, kt+2 resident after this
            __syncthreads();      // protect slot reuse
        }
    }

    // ------------------------------- epilogue -------------------------------
    const int r00 = mBase + wm * 64 + (l >> 2);
    const int cB  = nBase + wn * 48 + 2 * (l & 3);

    #pragma unroll
    for (int i = 0; i < 4; i++)
        #pragma unroll
        for (int j = 0; j < 6; j++) {
            const int c = cB + j * 8;
            const float b0 = __ldg(bias + c), b1 = __ldg(bias + c + 1);
            #pragma unroll
            for (int hh = 0; hh < 2; hh++) {
                const int r = r00 + i * 16 + hh * 8;
                const float v0 = acc[i][j][2 * hh]     + b0;
                const float v1 = acc[i][j][2 * hh + 1] + b1;
                if constexpr (HALF_OUT) {
                    *reinterpret_cast<__half2*>(oH + (size_t)r * ldo + c) =
                        __floats2half2_rn(v0, v1);
                } else {
                    *reinterpret_cast<float2*>(oF + (size_t)r * ldo + c) =
                        make_float2(v0, v1);
                }
            }
        }
}

// ---------------------------------------------------------------------------
// Host
// ---------------------------------------------------------------------------
extern "C" void kernel_launch(void* const* d_in, const int* in_sizes, int n_in,
                              void* d_out, int out_size) {
    const float* x  = (const float*)d_in[0];   // hidden_states (4096, 2880)
    const float* w1 = (const float*)d_in[3];   // gate_up_w (5760, 2880)
    const float* b1 = (const float*)d_in[4];   // gate_up_b (5760,)
    const float* w2 = (const float*)d_in[5];   // down_w (2880, 2880)
    const float* b2 = (const float*)d_in[6];   // down_b (2880,)
    float* out = (float*)d_out;                // (4096, 2880) fp32

    void *px, *pw1, *pw2, *pgu, *ph;
    cudaGetSymbolAddress(&px,  g_xh);
    cudaGetSymbolAddress(&pw1, g_w1h);
    cudaGetSymbolAddress(&pw2, g_w2h);
    cudaGetSymbolAddress(&pgu, g_gu);
    cudaGetSymbolAddress(&ph,  g_hh);

    // fp32 -> fp16
    {
        int n4 = (SEQ * HID) / 4;
        cvt_kernel<<<(n4 + 255) / 256, 256>>>((const float4*)x,  (uint2*)px,  n4);
        n4 = (NGU * HID) / 4;
        cvt_kernel<<<(n4 + 255) / 256, 256>>>((const float4*)w1, (uint2*)pw1, n4);
        n4 = (HID * INTER) / 4;
        cvt_kernel<<<(n4 + 255) / 256, 256>>>((const float4*)w2, (uint2*)pw2, n4);
    }

    cudaFuncSetAttribute(gemm_f16<true>,
                         cudaFuncAttributeMaxDynamicSharedMemorySize, SMEM_SZ);
    cudaFuncSetAttribute(gemm_f16<false>,
                         cudaFuncAttributeMaxDynamicSharedMemorySize, SMEM_SZ);

    // GEMM1: gateup = x @ W1^T + b1   (fp16, 4096 x 5760)
    gemm_f16<true><<<dim3(SEQ / BM, NGU / BN), 128, SMEM_SZ>>>(
        (const __half*)px, (const __half*)pw1, b1, (__half*)pgu, nullptr, NGU);

    // SiLU: h = gate * silu(up)   (fp16, 4096 x 2880)
    {
        int n8 = SEQ * INTER / 8;
        silu_kernel<<<(n8 + 255) / 256, 256>>>((const __half*)pgu, (__half*)ph);
    }

    // GEMM2: out = h @ W2^T + b2   (fp32, 4096 x 2880)
    gemm_f16<false><<<dim3(SEQ / BM, INTER / BN), 128, SMEM_SZ>>>(
        (const __half*)ph, (const __half*)pw2, b2, nullptr, out, HID);
}